// round 12
// baseline (speedup 1.0000x reference)
#include <cuda_runtime.h>

// LSTM T=512, B=4096, I=10, H=20.
// R10 = R8 structure (best so far): thread = (unit j, gate-pair, 2 rows),
// even lane (i,g), odd lane (f,o), 3 shfls route gates, every lane updates
// one row's (c,h). CHANGE: x lives in per-thread REGISTERS (prefetch t+1),
// no smem x staging, no stager role -> barrier protects only the h exchange.
// Weights register-resident; fma.rn.f32x2; tanh.approx; one barrier/step.

#define T_STEPS 512
#define BATCH   4096
#define ISZ     10
#define HSZ     20
#define ROWS_CTA 8
#define NTHREADS 160

typedef unsigned long long u64;

__device__ __forceinline__ u64 pack2(float x, float y) {
    u64 r; asm("mov.b64 %0, {%1,%2};" : "=l"(r) : "f"(x), "f"(y)); return r;
}
__device__ __forceinline__ void unpack2(u64 v, float& x, float& y) {
    asm("mov.b64 {%0,%1}, %2;" : "=f"(x), "=f"(y) : "l"(v));
}
__device__ __forceinline__ u64 ffma2(u64 a, u64 b, u64 c) {
    u64 r; asm("fma.rn.f32x2 %0, %1, %2, %3;" : "=l"(r) : "l"(a), "l"(b), "l"(c));
    return r;
}
__device__ __forceinline__ float tanh_fast(float x) {
    float y; asm("tanh.approx.f32 %0, %1;" : "=f"(y) : "f"(x)); return y;
}

#define HBUF_F (2 * ROWS_CTA * HSZ)        // 320 floats, double-buffered h

__global__ void __launch_bounds__(NTHREADS, 4) lstm_r10_kernel(
    const float* __restrict__ x,      // [T, B, I]
    const float* __restrict__ h0,     // [B, H]
    const float* __restrict__ c0,     // [B, H]
    const float* __restrict__ Wih,    // [4H, I]
    const float* __restrict__ Whh,    // [4H, H]
    const float* __restrict__ bih,    // [4H]
    const float* __restrict__ bhh,    // [4H]
    float* __restrict__ out,
    long long out_size)
{
    const int tid  = threadIdx.x;
    const int half = tid & 1;             // 0: (i,g)  1: (f,o)
    const int p    = tid >> 1;            // 0..79
    const int rg   = p / HSZ;             // 0..3
    const int j    = p % HSZ;
    const int rA   = rg;
    const int rB   = rg + 4;
    const int bA   = blockIdx.x * ROWS_CTA + rA;
    const int bB   = blockIdx.x * ROWS_CTA + rB;

    __shared__ __align__(16) float hbuf[HBUF_F];

    const int g0 = half ? 1 : 0;          // f | i   (sigmoid)
    const int g1 = half ? 3 : 2;          // o | g   (sigmoid | tanh)
    const float s1 = half ? 0.5f : 1.0f;
    const float o1 = 1.0f - s1;

    // ---- register-resident weights (2 gate-rows) ----
    u64 wx[2][5], wh[2][10], bias2[2];
    {
        const int rows[2] = {g0 * HSZ + j, g1 * HSZ + j};
#pragma unroll
        for (int q = 0; q < 2; q++) {
            const float* wr = Wih + rows[q] * ISZ;
#pragma unroll
            for (int k = 0; k < 5; k++)
                wx[q][k] = *reinterpret_cast<const u64*>(wr + 2 * k);
            const float* wr2 = Whh + rows[q] * HSZ;
#pragma unroll
            for (int k = 0; k < 10; k++)
                wh[q][k] = *reinterpret_cast<const u64*>(wr2 + 2 * k);
            bias2[q] = pack2(bih[rows[q]] + bhh[rows[q]], 0.0f);
        }
    }

    // ---- owned row for the state update: odd -> A, even -> B ----
    const int myrow = half ? rA : rB;
    const int bmy   = half ? bA : bB;

    float c_ = c0[(size_t)bmy * HSZ + j];
    float h_ = 0.0f;
    hbuf[myrow * HSZ + j] = h0[(size_t)bmy * HSZ + j];

    // ---- x in registers: both rows, current step ----
    const float* xA = x + (size_t)bA * ISZ;
    const float* xB = x + (size_t)bB * ISZ;
    const size_t x_step = (size_t)BATCH * ISZ;

    u64 xcA[5], xcB[5];
#pragma unroll
    for (int k = 0; k < 5; k++) {
        xcA[k] = *reinterpret_cast<const u64*>(xA + 2 * k);
        xcB[k] = *reinterpret_cast<const u64*>(xB + 2 * k);
    }
    __syncthreads();

    float* opmy = out + (size_t)bmy * HSZ + j;
    const size_t o_step = (size_t)BATCH * HSZ;

    for (int t = 0; t < T_STEPS; t++) {
        const int cur = t & 1;

        // prefetch x[t+1] into regs (consumed next iteration; covers full step)
        u64 xnA[5], xnB[5];
        {
            const size_t off = (size_t)((t + 1 < T_STEPS) ? t + 1 : t) * x_step;
            const float* qA = xA + off;
            const float* qB = xB + off;
#pragma unroll
            for (int k = 0; k < 5; k++) {
                xnA[k] = *reinterpret_cast<const u64*>(qA + 2 * k);
                xnB[k] = *reinterpret_cast<const u64*>(qB + 2 * k);
            }
        }

        // ---- projections ----
        u64 aA0 = bias2[0], aA1 = bias2[1], aB0 = bias2[0], aB1 = bias2[1];
#pragma unroll
        for (int k = 0; k < 5; k++) {
            aA0 = ffma2(wx[0][k], xcA[k], aA0);
            aA1 = ffma2(wx[1][k], xcA[k], aA1);
            aB0 = ffma2(wx[0][k], xcB[k], aB0);
            aB1 = ffma2(wx[1][k], xcB[k], aB1);
        }
        {
            const float* hA_ = hbuf + cur * (ROWS_CTA * HSZ) + rA * HSZ;
            const float* hB_ = hbuf + cur * (ROWS_CTA * HSZ) + rB * HSZ;
#pragma unroll
            for (int k4 = 0; k4 < 5; k4++) {
                const ulonglong2 va = *reinterpret_cast<const ulonglong2*>(hA_ + 4 * k4);
                const ulonglong2 vb = *reinterpret_cast<const ulonglong2*>(hB_ + 4 * k4);
                aA0 = ffma2(wh[0][2 * k4],     va.x, aA0);
                aA1 = ffma2(wh[1][2 * k4],     va.x, aA1);
                aA0 = ffma2(wh[0][2 * k4 + 1], va.y, aA0);
                aA1 = ffma2(wh[1][2 * k4 + 1], va.y, aA1);
                aB0 = ffma2(wh[0][2 * k4],     vb.x, aB0);
                aB1 = ffma2(wh[1][2 * k4],     vb.x, aB1);
                aB0 = ffma2(wh[0][2 * k4 + 1], vb.y, aB0);
                aB1 = ffma2(wh[1][2 * k4 + 1], vb.y, aB1);
            }
        }

        // ---- activations ----
        float lo, hi;
        unpack2(aA0, lo, hi);
        const float vA0 = fmaf(tanh_fast(0.5f * (lo + hi)), 0.5f, 0.5f); // i|f (A)
        unpack2(aA1, lo, hi);
        const float vA1 = fmaf(tanh_fast(s1 * (lo + hi)), s1, o1);       // g|o (A)
        unpack2(aB0, lo, hi);
        const float vB0 = fmaf(tanh_fast(0.5f * (lo + hi)), 0.5f, 0.5f); // i|f (B)
        unpack2(aB1, lo, hi);
        const float vB1 = fmaf(tanh_fast(s1 * (lo + hi)), s1, o1);       // g|o (B)

        // even lane: tA = iA*gA, tB = iB*gB
        const float tA = vA0 * vA1;
        const float tB = vB0 * vB1;

        // route: odd gets iA*gA; even gets fB, oB
        const float rAp = __shfl_xor_sync(0xFFFFFFFFu, tA,  1);
        const float rB0 = __shfl_xor_sync(0xFFFFFFFFu, vB0, 1);
        const float rB1 = __shfl_xor_sync(0xFFFFFFFFu, vB1, 1);

        const float f_eff = half ? vA0 : rB0;
        const float p_eff = half ? rAp : tB;
        const float o_eff = half ? vA1 : rB1;
        c_ = fmaf(f_eff, c_, p_eff);
        const float th = tanh_fast(c_);
        h_ = o_eff * th;

        // h STS first (barrier dependency), then fire-and-forget STG
        hbuf[(cur ^ 1) * (ROWS_CTA * HSZ) + myrow * HSZ + j] = h_;
        opmy[0] = h_;

        // rotate x regs
#pragma unroll
        for (int k = 0; k < 5; k++) { xcA[k] = xnA[k]; xcB[k] = xnB[k]; }

        __syncthreads();
        opmy += o_step;
    }

    // ---- final h, c ----
    const long long base = (long long)T_STEPS * BATCH * HSZ;
    if (out_size >= base + 2LL * BATCH * HSZ) {
        out[base + (size_t)bmy * HSZ + j] = h_;
        out[base + (size_t)BATCH * HSZ + (size_t)bmy * HSZ + j] = c_;
    }
}

extern "C" void kernel_launch(void* const* d_in, const int* in_sizes, int n_in,
                              void* d_out, int out_size) {
    const float* x   = (const float*)d_in[0];
    const float* h0  = (const float*)d_in[1];
    const float* c0  = (const float*)d_in[2];
    const float* Wih = (const float*)d_in[3];
    const float* Whh = (const float*)d_in[4];
    const float* bih = (const float*)d_in[5];
    const float* bhh = (const float*)d_in[6];
    float* out = (float*)d_out;

    dim3 grid(BATCH / ROWS_CTA);   // 512 CTAs -> one resident wave at 4 CTA/SM
    dim3 block(NTHREADS);          // 160 threads
    lstm_r10_kernel<<<grid, block>>>(x, h0, c0, Wih, Whh, bih, bhh,
                                     out, (long long)out_size);
}

// round 13
// speedup vs baseline: 1.0309x; 1.0309x over previous
#include <cuda_runtime.h>

// LSTM T=512, B=4096, I=10, H=20.
// R10 = R8 structure (best so far): thread = (unit j, gate-pair, 2 rows),
// even lane (i,g), odd lane (f,o), 3 shfls route gates, every lane updates
// one row's (c,h). CHANGE: x lives in per-thread REGISTERS (prefetch t+1),
// no smem x staging, no stager role -> barrier protects only the h exchange.
// Weights register-resident; fma.rn.f32x2; tanh.approx; one barrier/step.

#define T_STEPS 512
#define BATCH   4096
#define ISZ     10
#define HSZ     20
#define ROWS_CTA 8
#define NTHREADS 160

typedef unsigned long long u64;

__device__ __forceinline__ u64 pack2(float x, float y) {
    u64 r; asm("mov.b64 %0, {%1,%2};" : "=l"(r) : "f"(x), "f"(y)); return r;
}
__device__ __forceinline__ void unpack2(u64 v, float& x, float& y) {
    asm("mov.b64 {%0,%1}, %2;" : "=f"(x), "=f"(y) : "l"(v));
}
__device__ __forceinline__ u64 ffma2(u64 a, u64 b, u64 c) {
    u64 r; asm("fma.rn.f32x2 %0, %1, %2, %3;" : "=l"(r) : "l"(a), "l"(b), "l"(c));
    return r;
}
__device__ __forceinline__ float tanh_fast(float x) {
    float y; asm("tanh.approx.f32 %0, %1;" : "=f"(y) : "f"(x)); return y;
}

#define HBUF_F (2 * ROWS_CTA * HSZ)        // 320 floats, double-buffered h

__global__ void __launch_bounds__(NTHREADS, 4) lstm_r10_kernel(
    const float* __restrict__ x,      // [T, B, I]
    const float* __restrict__ h0,     // [B, H]
    const float* __restrict__ c0,     // [B, H]
    const float* __restrict__ Wih,    // [4H, I]
    const float* __restrict__ Whh,    // [4H, H]
    const float* __restrict__ bih,    // [4H]
    const float* __restrict__ bhh,    // [4H]
    float* __restrict__ out,
    long long out_size)
{
    const int tid  = threadIdx.x;
    const int half = tid & 1;             // 0: (i,g)  1: (f,o)
    const int p    = tid >> 1;            // 0..79
    const int rg   = p / HSZ;             // 0..3
    const int j    = p % HSZ;
    const int rA   = rg;
    const int rB   = rg + 4;
    const int bA   = blockIdx.x * ROWS_CTA + rA;
    const int bB   = blockIdx.x * ROWS_CTA + rB;

    __shared__ __align__(16) float hbuf[HBUF_F];

    const int g0 = half ? 1 : 0;          // f | i   (sigmoid)
    const int g1 = half ? 3 : 2;          // o | g   (sigmoid | tanh)
    const float s1 = half ? 0.5f : 1.0f;
    const float o1 = 1.0f - s1;

    // ---- register-resident weights (2 gate-rows) ----
    u64 wx[2][5], wh[2][10], bias2[2];
    {
        const int rows[2] = {g0 * HSZ + j, g1 * HSZ + j};
#pragma unroll
        for (int q = 0; q < 2; q++) {
            const float* wr = Wih + rows[q] * ISZ;
#pragma unroll
            for (int k = 0; k < 5; k++)
                wx[q][k] = *reinterpret_cast<const u64*>(wr + 2 * k);
            const float* wr2 = Whh + rows[q] * HSZ;
#pragma unroll
            for (int k = 0; k < 10; k++)
                wh[q][k] = *reinterpret_cast<const u64*>(wr2 + 2 * k);
            bias2[q] = pack2(bih[rows[q]] + bhh[rows[q]], 0.0f);
        }
    }

    // ---- owned row for the state update: odd -> A, even -> B ----
    const int myrow = half ? rA : rB;
    const int bmy   = half ? bA : bB;

    float c_ = c0[(size_t)bmy * HSZ + j];
    float h_ = 0.0f;
    hbuf[myrow * HSZ + j] = h0[(size_t)bmy * HSZ + j];

    // ---- x in registers: both rows, current step ----
    const float* xA = x + (size_t)bA * ISZ;
    const float* xB = x + (size_t)bB * ISZ;
    const size_t x_step = (size_t)BATCH * ISZ;

    u64 xcA[5], xcB[5];
#pragma unroll
    for (int k = 0; k < 5; k++) {
        xcA[k] = *reinterpret_cast<const u64*>(xA + 2 * k);
        xcB[k] = *reinterpret_cast<const u64*>(xB + 2 * k);
    }
    __syncthreads();

    float* opmy = out + (size_t)bmy * HSZ + j;
    const size_t o_step = (size_t)BATCH * HSZ;

    for (int t = 0; t < T_STEPS; t++) {
        const int cur = t & 1;

        // prefetch x[t+1] into regs (consumed next iteration; covers full step)
        u64 xnA[5], xnB[5];
        {
            const size_t off = (size_t)((t + 1 < T_STEPS) ? t + 1 : t) * x_step;
            const float* qA = xA + off;
            const float* qB = xB + off;
#pragma unroll
            for (int k = 0; k < 5; k++) {
                xnA[k] = *reinterpret_cast<const u64*>(qA + 2 * k);
                xnB[k] = *reinterpret_cast<const u64*>(qB + 2 * k);
            }
        }

        // ---- projections ----
        u64 aA0 = bias2[0], aA1 = bias2[1], aB0 = bias2[0], aB1 = bias2[1];
#pragma unroll
        for (int k = 0; k < 5; k++) {
            aA0 = ffma2(wx[0][k], xcA[k], aA0);
            aA1 = ffma2(wx[1][k], xcA[k], aA1);
            aB0 = ffma2(wx[0][k], xcB[k], aB0);
            aB1 = ffma2(wx[1][k], xcB[k], aB1);
        }
        {
            const float* hA_ = hbuf + cur * (ROWS_CTA * HSZ) + rA * HSZ;
            const float* hB_ = hbuf + cur * (ROWS_CTA * HSZ) + rB * HSZ;
#pragma unroll
            for (int k4 = 0; k4 < 5; k4++) {
                const ulonglong2 va = *reinterpret_cast<const ulonglong2*>(hA_ + 4 * k4);
                const ulonglong2 vb = *reinterpret_cast<const ulonglong2*>(hB_ + 4 * k4);
                aA0 = ffma2(wh[0][2 * k4],     va.x, aA0);
                aA1 = ffma2(wh[1][2 * k4],     va.x, aA1);
                aA0 = ffma2(wh[0][2 * k4 + 1], va.y, aA0);
                aA1 = ffma2(wh[1][2 * k4 + 1], va.y, aA1);
                aB0 = ffma2(wh[0][2 * k4],     vb.x, aB0);
                aB1 = ffma2(wh[1][2 * k4],     vb.x, aB1);
                aB0 = ffma2(wh[0][2 * k4 + 1], vb.y, aB0);
                aB1 = ffma2(wh[1][2 * k4 + 1], vb.y, aB1);
            }
        }

        // ---- activations ----
        float lo, hi;
        unpack2(aA0, lo, hi);
        const float vA0 = fmaf(tanh_fast(0.5f * (lo + hi)), 0.5f, 0.5f); // i|f (A)
        unpack2(aA1, lo, hi);
        const float vA1 = fmaf(tanh_fast(s1 * (lo + hi)), s1, o1);       // g|o (A)
        unpack2(aB0, lo, hi);
        const float vB0 = fmaf(tanh_fast(0.5f * (lo + hi)), 0.5f, 0.5f); // i|f (B)
        unpack2(aB1, lo, hi);
        const float vB1 = fmaf(tanh_fast(s1 * (lo + hi)), s1, o1);       // g|o (B)

        // even lane: tA = iA*gA, tB = iB*gB
        const float tA = vA0 * vA1;
        const float tB = vB0 * vB1;

        // route: odd gets iA*gA; even gets fB, oB
        const float rAp = __shfl_xor_sync(0xFFFFFFFFu, tA,  1);
        const float rB0 = __shfl_xor_sync(0xFFFFFFFFu, vB0, 1);
        const float rB1 = __shfl_xor_sync(0xFFFFFFFFu, vB1, 1);

        const float f_eff = half ? vA0 : rB0;
        const float p_eff = half ? rAp : tB;
        const float o_eff = half ? vA1 : rB1;
        c_ = fmaf(f_eff, c_, p_eff);
        const float th = tanh_fast(c_);
        h_ = o_eff * th;

        // h STS first (barrier dependency), then fire-and-forget STG
        hbuf[(cur ^ 1) * (ROWS_CTA * HSZ) + myrow * HSZ + j] = h_;
        opmy[0] = h_;

        // rotate x regs
#pragma unroll
        for (int k = 0; k < 5; k++) { xcA[k] = xnA[k]; xcB[k] = xnB[k]; }

        __syncthreads();
        opmy += o_step;
    }

    // ---- final h, c ----
    const long long base = (long long)T_STEPS * BATCH * HSZ;
    if (out_size >= base + 2LL * BATCH * HSZ) {
        out[base + (size_t)bmy * HSZ + j] = h_;
        out[base + (size_t)BATCH * HSZ + (size_t)bmy * HSZ + j] = c_;
    }
}

extern "C" void kernel_launch(void* const* d_in, const int* in_sizes, int n_in,
                              void* d_out, int out_size) {
    const float* x   = (const float*)d_in[0];
    const float* h0  = (const float*)d_in[1];
    const float* c0  = (const float*)d_in[2];
    const float* Wih = (const float*)d_in[3];
    const float* Whh = (const float*)d_in[4];
    const float* bih = (const float*)d_in[5];
    const float* bhh = (const float*)d_in[6];
    float* out = (float*)d_out;

    dim3 grid(BATCH / ROWS_CTA);   // 512 CTAs -> one resident wave at 4 CTA/SM
    dim3 block(NTHREADS);          // 160 threads
    lstm_r10_kernel<<<grid, block>>>(x, h0, c0, Wih, Whh, bih, bhh,
                                     out, (long long)out_size);
}

// round 14
// speedup vs baseline: 1.3106x; 1.2714x over previous
#include <cuda_runtime.h>

// LSTM T=512, B=4096, I=10, H=20.
// R11 = R8 (best: 406us) + t-loop unrolled by 2 (static double-buffer offsets
// as immediates), hoisted addressing, early shfl issue, streaming ld/st for
// x/out. Thread = (unit j, gate-pair, 2 rows); even lane (i,g), odd (f,o);
// 3 shfls route gates; every lane updates one row's (c,h). One barrier/step.

#define T_STEPS 512
#define BATCH   4096
#define ISZ     10
#define HSZ     20
#define ROWS_CTA 8
#define NTHREADS 160
#define XS_ROW  12
#define XS_BUF  (ROWS_CTA * XS_ROW)   // 96 floats per x buffer
#define HB      (ROWS_CTA * HSZ)      // 160 floats per h buffer

typedef unsigned long long u64;

__device__ __forceinline__ u64 pack2(float x, float y) {
    u64 r; asm("mov.b64 %0, {%1,%2};" : "=l"(r) : "f"(x), "f"(y)); return r;
}
__device__ __forceinline__ void unpack2(u64 v, float& x, float& y) {
    asm("mov.b64 {%0,%1}, %2;" : "=f"(x), "=f"(y) : "l"(v));
}
__device__ __forceinline__ u64 ffma2(u64 a, u64 b, u64 c) {
    u64 r; asm("fma.rn.f32x2 %0, %1, %2, %3;" : "=l"(r) : "l"(a), "l"(b), "l"(c));
    return r;
}
__device__ __forceinline__ float tanh_fast(float x) {
    float y; asm("tanh.approx.f32 %0, %1;" : "=f"(y) : "f"(x)); return y;
}

__global__ void __launch_bounds__(NTHREADS, 4) lstm_r11_kernel(
    const float* __restrict__ x,      // [T, B, I]
    const float* __restrict__ h0,     // [B, H]
    const float* __restrict__ c0,     // [B, H]
    const float* __restrict__ Wih,    // [4H, I]
    const float* __restrict__ Whh,    // [4H, H]
    const float* __restrict__ bih,    // [4H]
    const float* __restrict__ bhh,    // [4H]
    float* __restrict__ out,
    long long out_size)
{
    const int tid  = threadIdx.x;
    const int half = tid & 1;             // 0: (i,g)  1: (f,o)
    const int p    = tid >> 1;            // 0..79
    const int rg   = p / HSZ;             // 0..3
    const int j    = p % HSZ;
    const int rA   = rg;
    const int rB   = rg + 4;
    const int bA   = blockIdx.x * ROWS_CTA + rA;
    const int bB   = blockIdx.x * ROWS_CTA + rB;

    __shared__ __align__(16) float hbuf[2 * HB];      // h double buffer
    __shared__ __align__(16) float xs[2 * XS_BUF];    // x double buffer

    const int g0 = half ? 1 : 0;          // f | i   (sigmoid)
    const int g1 = half ? 3 : 2;          // o | g   (sigmoid | tanh)
    const float s1 = half ? 0.5f : 1.0f;
    const float o1 = 1.0f - s1;

    // ---- register-resident weights (2 gate-rows) ----
    u64 wx[2][5], wh[2][10], bias2[2];
    {
        const int rows[2] = {g0 * HSZ + j, g1 * HSZ + j};
#pragma unroll
        for (int q = 0; q < 2; q++) {
            const float* wr = Wih + rows[q] * ISZ;
#pragma unroll
            for (int k = 0; k < 5; k++)
                wx[q][k] = *reinterpret_cast<const u64*>(wr + 2 * k);
            const float* wr2 = Whh + rows[q] * HSZ;
#pragma unroll
            for (int k = 0; k < 10; k++)
                wh[q][k] = *reinterpret_cast<const u64*>(wr2 + 2 * k);
            bias2[q] = pack2(bih[rows[q]] + bhh[rows[q]], 0.0f);
        }
    }

    // ---- owned row for the state update: odd -> A, even -> B ----
    const int myrow = half ? rA : rB;
    const int bmy   = half ? bA : bB;

    float c_ = c0[(size_t)bmy * HSZ + j];
    float h_ = 0.0f;

    // ---- hoisted smem base pointers (buffer select via immediates) ----
    const float* const hA_ = hbuf + rA * HSZ;
    const float* const hB_ = hbuf + rB * HSZ;
    float* const hw        = hbuf + myrow * HSZ + j;
    const float* const xrA = xs + rA * XS_ROW;
    const float* const xrB = xs + rB * XS_ROW;

    // ---- x staging role: 8 threads/warp (tid%4==3), 40 slots ----
    const bool stager = ((tid & 3) == 3);
    const int  slot   = tid >> 2;             // 0..39
    const int  srow   = slot / 5;
    const int  schk   = slot - srow * 5;
    const int  sgoff  = srow * ISZ + schk * 2;       // gmem float offset
    float* const xw   = xs + srow * XS_ROW + schk * 2;

    const float* xcta = x + (size_t)blockIdx.x * ROWS_CTA * ISZ;
    const size_t x_step = (size_t)BATCH * ISZ;

    // prime: h(0) -> hbuf[0..], x[0] -> xs[0..]
    hw[0] = h0[(size_t)bmy * HSZ + j];
    if (stager)
        *reinterpret_cast<u64*>(xw) =
            __ldcs(reinterpret_cast<const u64*>(xcta + sgoff));
    __syncthreads();

    float* opmy = out + (size_t)bmy * HSZ + j;
    const size_t o_step = (size_t)BATCH * HSZ;

    const float* xq = xcta + x_step;   // -> x[t+1] for body 0 (t even)

    // ================= one step body (offsets are immediates) ==============
#define STEP_BODY(HIN, HOUT, XIN, XOUT, XQPTR)                                 \
    {                                                                          \
        u64 xpre = 0ull;                                                       \
        if (stager)                                                            \
            xpre = __ldcs(reinterpret_cast<const u64*>((XQPTR) + sgoff));      \
        u64 aA0 = bias2[0], aA1 = bias2[1], aB0 = bias2[0], aB1 = bias2[1];    \
        {                                                                      \
            const ulonglong2 a01 = *reinterpret_cast<const ulonglong2*>(xrA + (XIN));     \
            const ulonglong2 a23 = *reinterpret_cast<const ulonglong2*>(xrA + (XIN) + 4); \
            const u64        a4  = *reinterpret_cast<const u64*>(xrA + (XIN) + 8);        \
            const ulonglong2 b01 = *reinterpret_cast<const ulonglong2*>(xrB + (XIN));     \
            const ulonglong2 b23 = *reinterpret_cast<const ulonglong2*>(xrB + (XIN) + 4); \
            const u64        b4  = *reinterpret_cast<const u64*>(xrB + (XIN) + 8);        \
            aA0 = ffma2(wx[0][0], a01.x, aA0);  aA1 = ffma2(wx[1][0], a01.x, aA1);        \
            aA0 = ffma2(wx[0][1], a01.y, aA0);  aA1 = ffma2(wx[1][1], a01.y, aA1);        \
            aA0 = ffma2(wx[0][2], a23.x, aA0);  aA1 = ffma2(wx[1][2], a23.x, aA1);        \
            aA0 = ffma2(wx[0][3], a23.y, aA0);  aA1 = ffma2(wx[1][3], a23.y, aA1);        \
            aA0 = ffma2(wx[0][4], a4,    aA0);  aA1 = ffma2(wx[1][4], a4,    aA1);        \
            aB0 = ffma2(wx[0][0], b01.x, aB0);  aB1 = ffma2(wx[1][0], b01.x, aB1);        \
            aB0 = ffma2(wx[0][1], b01.y, aB0);  aB1 = ffma2(wx[1][1], b01.y, aB1);        \
            aB0 = ffma2(wx[0][2], b23.x, aB0);  aB1 = ffma2(wx[1][2], b23.x, aB1);        \
            aB0 = ffma2(wx[0][3], b23.y, aB0);  aB1 = ffma2(wx[1][3], b23.y, aB1);        \
            aB0 = ffma2(wx[0][4], b4,    aB0);  aB1 = ffma2(wx[1][4], b4,    aB1);        \
        }                                                                      \
        _Pragma("unroll")                                                      \
        for (int k4 = 0; k4 < 5; k4++) {                                       \
            const ulonglong2 va = *reinterpret_cast<const ulonglong2*>(hA_ + (HIN) + 4 * k4); \
            const ulonglong2 vb = *reinterpret_cast<const ulonglong2*>(hB_ + (HIN) + 4 * k4); \
            aA0 = ffma2(wh[0][2 * k4],     va.x, aA0);                         \
            aA1 = ffma2(wh[1][2 * k4],     va.x, aA1);                         \
            aA0 = ffma2(wh[0][2 * k4 + 1], va.y, aA0);                         \
            aA1 = ffma2(wh[1][2 * k4 + 1], va.y, aA1);                         \
            aB0 = ffma2(wh[0][2 * k4],     vb.x, aB0);                         \
            aB1 = ffma2(wh[1][2 * k4],     vb.x, aB1);                         \
            aB0 = ffma2(wh[0][2 * k4 + 1], vb.y, aB0);                         \
            aB1 = ffma2(wh[1][2 * k4 + 1], vb.y, aB1);                         \
        }                                                                      \
        float lo, hi;                                                          \
        /* row B first so its shfls overlap row A activations */               \
        unpack2(aB0, lo, hi);                                                  \
        const float vB0 = fmaf(tanh_fast(0.5f * (lo + hi)), 0.5f, 0.5f);       \
        unpack2(aB1, lo, hi);                                                  \
        const float vB1 = fmaf(tanh_fast(s1 * (lo + hi)), s1, o1);             \
        const float rB0 = __shfl_xor_sync(0xFFFFFFFFu, vB0, 1);                \
        const float rB1 = __shfl_xor_sync(0xFFFFFFFFu, vB1, 1);                \
        unpack2(aA0, lo, hi);                                                  \
        const float vA0 = fmaf(tanh_fast(0.5f * (lo + hi)), 0.5f, 0.5f);       \
        unpack2(aA1, lo, hi);                                                  \
        const float vA1 = fmaf(tanh_fast(s1 * (lo + hi)), s1, o1);             \
        const float tA  = vA0 * vA1;                                           \
        const float tB  = vB0 * vB1;                                           \
        const float rAp = __shfl_xor_sync(0xFFFFFFFFu, tA, 1);                 \
        const float f_eff = half ? vA0 : rB0;                                  \
        const float p_eff = half ? rAp : tB;                                   \
        const float o_eff = half ? vA1 : rB1;                                  \
        c_ = fmaf(f_eff, c_, p_eff);                                           \
        h_ = o_eff * tanh_fast(c_);                                            \
        hw[(HOUT)] = h_;                                                       \
        __stcs(opmy, h_);                                                      \
        if (stager)                                                            \
            *reinterpret_cast<u64*>(xw + (XOUT)) = xpre;                       \
        __syncthreads();                                                       \
        opmy += o_step;                                                        \
    }
    // ========================================================================

    for (int it = 0; it < T_STEPS / 2; ++it) {
        // body 0 (even t): h in buf0 -> buf1, x in buf0, prefetch x[t+1] -> buf1
        STEP_BODY(0, HB, 0, XS_BUF, xq);

        // body 1 (odd t): h in buf1 -> buf0, x in buf1, prefetch x[t+2] -> buf0
        const float* xq2 = (it == T_STEPS / 2 - 1) ? xq : (xq + x_step);
        STEP_BODY(HB, 0, XS_BUF, 0, xq2);

        xq += 2 * x_step;
    }
#undef STEP_BODY

    // ---- final h, c appended after outputs ----
    const long long base = (long long)T_STEPS * BATCH * HSZ;
    if (out_size >= base + 2LL * BATCH * HSZ) {
        out[base + (size_t)bmy * HSZ + j] = h_;
        out[base + (size_t)BATCH * HSZ + (size_t)bmy * HSZ + j] = c_;
    }
}

extern "C" void kernel_launch(void* const* d_in, const int* in_sizes, int n_in,
                              void* d_out, int out_size) {
    const float* x   = (const float*)d_in[0];
    const float* h0  = (const float*)d_in[1];
    const float* c0  = (const float*)d_in[2];
    const float* Wih = (const float*)d_in[3];
    const float* Whh = (const float*)d_in[4];
    const float* bih = (const float*)d_in[5];
    const float* bhh = (const float*)d_in[6];
    float* out = (float*)d_out;

    dim3 grid(BATCH / ROWS_CTA);   // 512 CTAs -> one resident wave at 4 CTA/SM
    dim3 block(NTHREADS);          // 160 threads
    lstm_r11_kernel<<<grid, block>>>(x, h0, c0, Wih, Whh, bih, bhh,
                                     out, (long long)out_size);
}

// round 15
// speedup vs baseline: 1.3624x; 1.0395x over previous
#include <cuda_runtime.h>

// LSTM T=512, B=4096, I=10, H=20.
// R12 = R11 (400us) with three surgical changes:
//  (1) stager LDG prefetch distance extended by 1 full step (LDG x(t+2) at
//      body t, STS at body t+1 tail) -> ~1.9 bodies of latency cover.
//  (2) __ldcg for x (x fits in L2; don't stream-evict), __stcs only for out.
//  (3) h-projection LDS.128 front-batched (MLP) before the ffma block.
// Structure unchanged: thread = (unit j, gate-pair, 2 rows); even lane (i,g),
// odd (f,o); 3 shfls; one barrier/step; unroll x2 with immediate offsets.

#define T_STEPS 512
#define BATCH   4096
#define ISZ     10
#define HSZ     20
#define ROWS_CTA 8
#define NTHREADS 160
#define XS_ROW  12
#define XS_BUF  (ROWS_CTA * XS_ROW)   // 96 floats per x buffer
#define HB      (ROWS_CTA * HSZ)      // 160 floats per h buffer

typedef unsigned long long u64;

__device__ __forceinline__ u64 pack2(float x, float y) {
    u64 r; asm("mov.b64 %0, {%1,%2};" : "=l"(r) : "f"(x), "f"(y)); return r;
}
__device__ __forceinline__ void unpack2(u64 v, float& x, float& y) {
    asm("mov.b64 {%0,%1}, %2;" : "=f"(x), "=f"(y) : "l"(v));
}
__device__ __forceinline__ u64 ffma2(u64 a, u64 b, u64 c) {
    u64 r; asm("fma.rn.f32x2 %0, %1, %2, %3;" : "=l"(r) : "l"(a), "l"(b), "l"(c));
    return r;
}
__device__ __forceinline__ float tanh_fast(float x) {
    float y; asm("tanh.approx.f32 %0, %1;" : "=f"(y) : "f"(x)); return y;
}

__global__ void __launch_bounds__(NTHREADS, 4) lstm_r12_kernel(
    const float* __restrict__ x,      // [T, B, I]
    const float* __restrict__ h0,     // [B, H]
    const float* __restrict__ c0,     // [B, H]
    const float* __restrict__ Wih,    // [4H, I]
    const float* __restrict__ Whh,    // [4H, H]
    const float* __restrict__ bih,    // [4H]
    const float* __restrict__ bhh,    // [4H]
    float* __restrict__ out,
    long long out_size)
{
    const int tid  = threadIdx.x;
    const int half = tid & 1;             // 0: (i,g)  1: (f,o)
    const int p    = tid >> 1;            // 0..79
    const int rg   = p / HSZ;             // 0..3
    const int j    = p % HSZ;
    const int rA   = rg;
    const int rB   = rg + 4;
    const int bA   = blockIdx.x * ROWS_CTA + rA;
    const int bB   = blockIdx.x * ROWS_CTA + rB;

    __shared__ __align__(16) float hbuf[2 * HB];      // h double buffer
    __shared__ __align__(16) float xs[2 * XS_BUF];    // x double buffer

    const int g0 = half ? 1 : 0;          // f | i   (sigmoid)
    const int g1 = half ? 3 : 2;          // o | g   (sigmoid | tanh)
    const float s1 = half ? 0.5f : 1.0f;
    const float o1 = 1.0f - s1;

    // ---- register-resident weights (2 gate-rows) ----
    u64 wx[2][5], wh[2][10], bias2[2];
    {
        const int rows[2] = {g0 * HSZ + j, g1 * HSZ + j};
#pragma unroll
        for (int q = 0; q < 2; q++) {
            const float* wr = Wih + rows[q] * ISZ;
#pragma unroll
            for (int k = 0; k < 5; k++)
                wx[q][k] = *reinterpret_cast<const u64*>(wr + 2 * k);
            const float* wr2 = Whh + rows[q] * HSZ;
#pragma unroll
            for (int k = 0; k < 10; k++)
                wh[q][k] = *reinterpret_cast<const u64*>(wr2 + 2 * k);
            bias2[q] = pack2(bih[rows[q]] + bhh[rows[q]], 0.0f);
        }
    }

    // ---- owned row for the state update: odd -> A, even -> B ----
    const int myrow = half ? rA : rB;
    const int bmy   = half ? bA : bB;

    float c_ = c0[(size_t)bmy * HSZ + j];
    float h_ = 0.0f;

    // ---- hoisted smem base pointers ----
    const float* const hA_ = hbuf + rA * HSZ;
    const float* const hB_ = hbuf + rB * HSZ;
    float* const hw        = hbuf + myrow * HSZ + j;
    const float* const xrA = xs + rA * XS_ROW;
    const float* const xrB = xs + rB * XS_ROW;

    // ---- x staging role: 8 threads/warp (tid%4==3), 40 slots ----
    const bool stager = ((tid & 3) == 3);
    const int  slot   = tid >> 2;             // 0..39
    const int  srow   = slot / 5;
    const int  schk   = slot - srow * 5;
    const int  sgoff  = srow * ISZ + schk * 2;       // gmem float offset
    float* const xw   = xs + srow * XS_ROW + schk * 2;

    const float* xcta = x + (size_t)blockIdx.x * ROWS_CTA * ISZ;
    const size_t x_step = (size_t)BATCH * ISZ;
    const float* const xclamp = xcta + (size_t)(T_STEPS - 1) * x_step;

    // prime: h(0) -> hbuf[0..]; x[0] -> xs buf0 (direct); xp = x[1] (STS at
    // body-0 tail into buf1). Pipeline invariant: entering body t, xp holds
    // x(t+1); body t issues LDG x(t+2).
    u64 xp = 0ull;
    hw[0] = h0[(size_t)bmy * HSZ + j];
    if (stager) {
        *reinterpret_cast<u64*>(xw) =
            __ldcg(reinterpret_cast<const u64*>(xcta + sgoff));
        xp = __ldcg(reinterpret_cast<const u64*>(xcta + x_step + sgoff));
    }
    __syncthreads();

    float* opmy = out + (size_t)bmy * HSZ + j;
    const size_t o_step = (size_t)BATCH * HSZ;

    const float* xq = xcta + 2 * x_step;   // -> x(t+2) for body 0 (t=0)

    // ================= one step body (offsets are immediates) ==============
#define STEP_BODY(HIN, HOUT, XIN, XOUT, XQPTR)                                 \
    {                                                                          \
        u64 xnew = 0ull;                                                       \
        if (stager)                                                            \
            xnew = __ldcg(reinterpret_cast<const u64*>((XQPTR) + sgoff));      \
        /* front-batch all smem loads (MLP) */                                 \
        const ulonglong2 a01 = *reinterpret_cast<const ulonglong2*>(xrA + (XIN));     \
        const ulonglong2 a23 = *reinterpret_cast<const ulonglong2*>(xrA + (XIN) + 4); \
        const u64        a4  = *reinterpret_cast<const u64*>(xrA + (XIN) + 8);        \
        const ulonglong2 b01 = *reinterpret_cast<const ulonglong2*>(xrB + (XIN));     \
        const ulonglong2 b23 = *reinterpret_cast<const ulonglong2*>(xrB + (XIN) + 4); \
        const u64        b4  = *reinterpret_cast<const u64*>(xrB + (XIN) + 8);        \
        ulonglong2 va[5], vb[5];                                               \
        _Pragma("unroll")                                                      \
        for (int k4 = 0; k4 < 5; k4++) {                                       \
            va[k4] = *reinterpret_cast<const ulonglong2*>(hA_ + (HIN) + 4 * k4); \
            vb[k4] = *reinterpret_cast<const ulonglong2*>(hB_ + (HIN) + 4 * k4); \
        }                                                                      \
        u64 aA0 = bias2[0], aA1 = bias2[1], aB0 = bias2[0], aB1 = bias2[1];    \
        aA0 = ffma2(wx[0][0], a01.x, aA0);  aA1 = ffma2(wx[1][0], a01.x, aA1); \
        aA0 = ffma2(wx[0][1], a01.y, aA0);  aA1 = ffma2(wx[1][1], a01.y, aA1); \
        aA0 = ffma2(wx[0][2], a23.x, aA0);  aA1 = ffma2(wx[1][2], a23.x, aA1); \
        aA0 = ffma2(wx[0][3], a23.y, aA0);  aA1 = ffma2(wx[1][3], a23.y, aA1); \
        aA0 = ffma2(wx[0][4], a4,    aA0);  aA1 = ffma2(wx[1][4], a4,    aA1); \
        aB0 = ffma2(wx[0][0], b01.x, aB0);  aB1 = ffma2(wx[1][0], b01.x, aB1); \
        aB0 = ffma2(wx[0][1], b01.y, aB0);  aB1 = ffma2(wx[1][1], b01.y, aB1); \
        aB0 = ffma2(wx[0][2], b23.x, aB0);  aB1 = ffma2(wx[1][2], b23.x, aB1); \
        aB0 = ffma2(wx[0][3], b23.y, aB0);  aB1 = ffma2(wx[1][3], b23.y, aB1); \
        aB0 = ffma2(wx[0][4], b4,    aB0);  aB1 = ffma2(wx[1][4], b4,    aB1); \
        _Pragma("unroll")                                                      \
        for (int k4 = 0; k4 < 5; k4++) {                                       \
            aA0 = ffma2(wh[0][2 * k4],     va[k4].x, aA0);                     \
            aA1 = ffma2(wh[1][2 * k4],     va[k4].x, aA1);                     \
            aA0 = ffma2(wh[0][2 * k4 + 1], va[k4].y, aA0);                     \
            aA1 = ffma2(wh[1][2 * k4 + 1], va[k4].y, aA1);                     \
            aB0 = ffma2(wh[0][2 * k4],     vb[k4].x, aB0);                     \
            aB1 = ffma2(wh[1][2 * k4],     vb[k4].x, aB1);                     \
            aB0 = ffma2(wh[0][2 * k4 + 1], vb[k4].y, aB0);                     \
            aB1 = ffma2(wh[1][2 * k4 + 1], vb[k4].y, aB1);                     \
        }                                                                      \
        float lo, hi;                                                          \
        /* row B first so its shfls overlap row A activations */               \
        unpack2(aB0, lo, hi);                                                  \
        const float vB0 = fmaf(tanh_fast(0.5f * (lo + hi)), 0.5f, 0.5f);       \
        unpack2(aB1, lo, hi);                                                  \
        const float vB1 = fmaf(tanh_fast(s1 * (lo + hi)), s1, o1);             \
        const float rB0 = __shfl_xor_sync(0xFFFFFFFFu, vB0, 1);                \
        const float rB1 = __shfl_xor_sync(0xFFFFFFFFu, vB1, 1);                \
        unpack2(aA0, lo, hi);                                                  \
        const float vA0 = fmaf(tanh_fast(0.5f * (lo + hi)), 0.5f, 0.5f);       \
        unpack2(aA1, lo, hi);                                                  \
        const float vA1 = fmaf(tanh_fast(s1 * (lo + hi)), s1, o1);             \
        const float tA  = vA0 * vA1;                                           \
        const float tB  = vB0 * vB1;                                           \
        const float rAp = __shfl_xor_sync(0xFFFFFFFFu, tA, 1);                 \
        const float f_eff = half ? vA0 : rB0;                                  \
        const float p_eff = half ? rAp : tB;                                   \
        const float o_eff = half ? vA1 : rB1;                                  \
        c_ = fmaf(f_eff, c_, p_eff);                                           \
        h_ = o_eff * tanh_fast(c_);                                            \
        hw[(HOUT)] = h_;                                                       \
        __stcs(opmy, h_);                                                      \
        if (stager)                                                            \
            *reinterpret_cast<u64*>(xw + (XOUT)) = xp;                         \
        xp = xnew;                                                             \
        __syncthreads();                                                       \
        opmy += o_step;                                                        \
    }
    // ========================================================================

    for (int it = 0; it < T_STEPS / 2; ++it) {
        // body 0 (t=2it):   h buf0->buf1, x from buf0, STS x(t+1)->buf1,
        //                   LDG x(t+2) (clamped)
        const float* xq0 = (xq <= xclamp) ? xq : xclamp;
        STEP_BODY(0, HB, 0, XS_BUF, xq0);

        // body 1 (t=2it+1): h buf1->buf0, x from buf1, STS x(t+1)->buf0,
        //                   LDG x(t+2) (clamped)
        const float* xq1 = (xq + x_step <= xclamp) ? (xq + x_step) : xclamp;
        STEP_BODY(HB, 0, XS_BUF, 0, xq1);

        xq += 2 * x_step;
    }
#undef STEP_BODY

    // ---- final h, c appended after outputs ----
    const long long base = (long long)T_STEPS * BATCH * HSZ;
    if (out_size >= base + 2LL * BATCH * HSZ) {
        out[base + (size_t)bmy * HSZ + j] = h_;
        out[base + (size_t)BATCH * HSZ + (size_t)bmy * HSZ + j] = c_;
    }
}

extern "C" void kernel_launch(void* const* d_in, const int* in_sizes, int n_in,
                              void* d_out, int out_size) {
    const float* x   = (const float*)d_in[0];
    const float* h0  = (const float*)d_in[1];
    const float* c0  = (const float*)d_in[2];
    const float* Wih = (const float*)d_in[3];
    const float* Whh = (const float*)d_in[4];
    const float* bih = (const float*)d_in[5];
    const float* bhh = (const float*)d_in[6];
    float* out = (float*)d_out;

    dim3 grid(BATCH / ROWS_CTA);   // 512 CTAs -> one resident wave at 4 CTA/SM
    dim3 block(NTHREADS);          // 160 threads
    lstm_r12_kernel<<<grid, block>>>(x, h0, c0, Wih, Whh, bih, bhh,
                                     out, (long long)out_size);
}